// round 1
// baseline (speedup 1.0000x reference)
#include <cuda_runtime.h>
#include <cuda_bf16.h>

// Problem constants
#define BB 2
#define SS 2048
#define DD 1024
#define HH 16
#define DK 64
#define MT (BB*SS)      // 4096 rows of tokens

// Scratch (device globals — no allocation allowed in kernel_launch)
__device__ float g_Qh[BB*HH*SS*DK];   // [B,H,S,DK]
__device__ float g_Kh[BB*HH*SS*DK];
__device__ float g_Vh[BB*HH*SS*DK];
__device__ float g_Ctx[BB*SS*DD];     // [B,S,D] attention output (pre-Wo)

// ---------------------------------------------------------------------------
// SGEMM: C[M=4096, N=1024] = A[4096,1024] @ W[1024,1024] + bias
// 128x128 block tile, BK=8, 256 threads, 8x8 microtile.
// MODE 0: write C row-major [M,N] (final output)
// MODE 1: write head-split layout [B,H,S,DK] (QKV projections)
// ---------------------------------------------------------------------------
template<int MODE>
__global__ __launch_bounds__(256, 2)
void sgemm_proj(const float* __restrict__ A, const float* __restrict__ W,
                const float* __restrict__ bias, float* __restrict__ C)
{
    const int K = DD, N = DD;
    __shared__ float As[8*128];   // [k][m] transposed
    __shared__ float Bs[8*128];   // [k][n]

    const int tid  = threadIdx.x;
    const int row0 = blockIdx.y * 128;
    const int col0 = blockIdx.x * 128;

    const int arow = tid >> 1;          // 0..127
    const int acol = (tid & 1) * 4;     // 0 or 4
    const int brow = tid >> 5;          // 0..7
    const int bcol = (tid & 31) * 4;    // 0..124

    const int tr = (tid >> 4) << 3;     // 0..120
    const int tc = (tid & 15) << 3;

    float acc[8][8];
    #pragma unroll
    for (int i = 0; i < 8; i++)
        #pragma unroll
        for (int j = 0; j < 8; j++) acc[i][j] = 0.f;

    for (int k0 = 0; k0 < K; k0 += 8) {
        float4 av = *(const float4*)&A[(size_t)(row0 + arow) * K + k0 + acol];
        As[(acol+0)*128 + arow] = av.x;
        As[(acol+1)*128 + arow] = av.y;
        As[(acol+2)*128 + arow] = av.z;
        As[(acol+3)*128 + arow] = av.w;
        *(float4*)&Bs[brow*128 + bcol] =
            *(const float4*)&W[(size_t)(k0 + brow) * N + col0 + bcol];
        __syncthreads();

        #pragma unroll
        for (int k = 0; k < 8; k++) {
            float a[8], b[8];
            *(float4*)(a)   = *(const float4*)&As[k*128 + tr];
            *(float4*)(a+4) = *(const float4*)&As[k*128 + tr + 4];
            *(float4*)(b)   = *(const float4*)&Bs[k*128 + tc];
            *(float4*)(b+4) = *(const float4*)&Bs[k*128 + tc + 4];
            #pragma unroll
            for (int i = 0; i < 8; i++)
                #pragma unroll
                for (int j = 0; j < 8; j++)
                    acc[i][j] = fmaf(a[i], b[j], acc[i][j]);
        }
        __syncthreads();
    }

    // epilogue
    #pragma unroll
    for (int i = 0; i < 8; i++) {
        const int t = row0 + tr + i;          // token index
        #pragma unroll
        for (int j = 0; j < 8; j++) {
            const int col = col0 + tc + j;
            float v = acc[i][j] + bias[col];
            if (MODE == 0) {
                C[(size_t)t * DD + col] = v;
            } else {
                const int b  = t >> 11;       // /S
                const int s  = t & (SS-1);
                const int h  = col >> 6;      // /DK
                const int dk = col & (DK-1);
                C[(((size_t)(b*HH + h)) * SS + s) * DK + dk] = v;
            }
        }
    }
}

// ---------------------------------------------------------------------------
// Causal flash attention, fp32. One CTA = one (b,h) x 64-query tile.
// 256 threads (16x16 logical), 4x4 fragments.
// smem: QsT [d][row], KP (KsT [d][key] overlaid with Ps [row][key]), Vs [key][dk]
// ---------------------------------------------------------------------------
__global__ __launch_bounds__(256, 4)
void attn_causal(const float* __restrict__ Qh, const float* __restrict__ Kh,
                 const float* __restrict__ Vh, float* __restrict__ Ctx)
{
    __shared__ float QsT[64*64];
    __shared__ float KP [64*64];
    __shared__ float Vs [64*64];

    const int qt = blockIdx.x;            // query tile 0..31
    const int bh = blockIdx.y;            // 0..31
    const int b  = bh >> 4;
    const int h  = bh & (HH-1);

    const float* Qp = Qh + (size_t)bh * SS * DK;
    const float* Kp = Kh + (size_t)bh * SS * DK;
    const float* Vp = Vh + (size_t)bh * SS * DK;

    const int tid = threadIdx.x;
    const int ty  = tid >> 4;
    const int tx  = tid & 15;
    const int r0  = ty * 4;               // local query rows
    const int c0  = tx * 4;               // local key cols / dk cols

    // Load Q tile transposed: QsT[d][row]
    #pragma unroll
    for (int u = 0; u < 4; u++) {
        int idx4 = tid + 256*u;           // 0..1023
        int row  = idx4 >> 4;
        int d0   = (idx4 & 15) * 4;
        float4 v = *(const float4*)&Qp[(size_t)(qt*64 + row) * DK + d0];
        QsT[(d0+0)*64 + row] = v.x;
        QsT[(d0+1)*64 + row] = v.y;
        QsT[(d0+2)*64 + row] = v.z;
        QsT[(d0+3)*64 + row] = v.w;
    }

    float o[4][4];
    float m[4], l[4];
    #pragma unroll
    for (int i = 0; i < 4; i++) {
        m[i] = -1e30f; l[i] = 0.f;
        #pragma unroll
        for (int j = 0; j < 4; j++) o[i][j] = 0.f;
    }
    const float scale = 0.125f;           // 1/sqrt(64)

    for (int kt = 0; kt <= qt; kt++) {
        // Load K (transposed) and V (natural)
        #pragma unroll
        for (int u = 0; u < 4; u++) {
            int idx4 = tid + 256*u;
            int key  = idx4 >> 4;
            int d0   = (idx4 & 15) * 4;
            float4 kv = *(const float4*)&Kp[(size_t)(kt*64 + key) * DK + d0];
            KP[(d0+0)*64 + key] = kv.x;
            KP[(d0+1)*64 + key] = kv.y;
            KP[(d0+2)*64 + key] = kv.z;
            KP[(d0+3)*64 + key] = kv.w;
            *(float4*)&Vs[key*64 + d0] =
                *(const float4*)&Vp[(size_t)(kt*64 + key) * DK + d0];
        }
        __syncthreads();

        // S = Q @ K^T (frag 4x4)
        float sfrag[4][4];
        #pragma unroll
        for (int i = 0; i < 4; i++)
            #pragma unroll
            for (int j = 0; j < 4; j++) sfrag[i][j] = 0.f;

        #pragma unroll 8
        for (int d = 0; d < 64; d++) {
            float4 qv = *(const float4*)&QsT[d*64 + r0];
            float4 kv = *(const float4*)&KP [d*64 + c0];
            float qa[4] = {qv.x, qv.y, qv.z, qv.w};
            float ka[4] = {kv.x, kv.y, kv.z, kv.w};
            #pragma unroll
            for (int i = 0; i < 4; i++)
                #pragma unroll
                for (int j = 0; j < 4; j++)
                    sfrag[i][j] = fmaf(qa[i], ka[j], sfrag[i][j]);
        }
        __syncthreads();   // done reading K; KP becomes P buffer

        // scale + causal mask (diagonal tile only)
        #pragma unroll
        for (int i = 0; i < 4; i++)
            #pragma unroll
            for (int j = 0; j < 4; j++) {
                float v = sfrag[i][j] * scale;
                if (kt == qt && (c0 + j) > (r0 + i)) v = -1e30f;
                sfrag[i][j] = v;
            }

        // online softmax per row, write P into KP ([row][key])
        #pragma unroll
        for (int i = 0; i < 4; i++) {
            float mloc = sfrag[i][0];
            #pragma unroll
            for (int j = 1; j < 4; j++) mloc = fmaxf(mloc, sfrag[i][j]);
            #pragma unroll
            for (int off = 8; off >= 1; off >>= 1)
                mloc = fmaxf(mloc, __shfl_xor_sync(0xffffffffu, mloc, off));
            float mn = fmaxf(m[i], mloc);
            float corr = __expf(m[i] - mn);
            float ls = 0.f;
            #pragma unroll
            for (int j = 0; j < 4; j++) {
                float p = __expf(sfrag[i][j] - mn);
                sfrag[i][j] = p;
                ls += p;
            }
            #pragma unroll
            for (int off = 8; off >= 1; off >>= 1)
                ls += __shfl_xor_sync(0xffffffffu, ls, off);
            l[i] = l[i] * corr + ls;
            m[i] = mn;
            #pragma unroll
            for (int j = 0; j < 4; j++) o[i][j] *= corr;
            #pragma unroll
            for (int j = 0; j < 4; j++)
                KP[(r0+i)*64 + (c0+j)] = sfrag[i][j];
        }
        __syncthreads();

        // O += P @ V
        #pragma unroll 8
        for (int kk = 0; kk < 64; kk++) {
            float p0 = KP[(r0+0)*64 + kk];
            float p1 = KP[(r0+1)*64 + kk];
            float p2 = KP[(r0+2)*64 + kk];
            float p3 = KP[(r0+3)*64 + kk];
            float4 vv = *(const float4*)&Vs[kk*64 + c0];
            float va[4] = {vv.x, vv.y, vv.z, vv.w};
            #pragma unroll
            for (int j = 0; j < 4; j++) {
                o[0][j] = fmaf(p0, va[j], o[0][j]);
                o[1][j] = fmaf(p1, va[j], o[1][j]);
                o[2][j] = fmaf(p2, va[j], o[2][j]);
                o[3][j] = fmaf(p3, va[j], o[3][j]);
            }
        }
        __syncthreads();
    }

    // normalize and write context in concat layout [B,S,D]
    #pragma unroll
    for (int i = 0; i < 4; i++) {
        const int q = qt*64 + r0 + i;
        float inv = 1.f / l[i];
        float4 w;
        w.x = o[i][0]*inv; w.y = o[i][1]*inv; w.z = o[i][2]*inv; w.w = o[i][3]*inv;
        *(float4*)&Ctx[((size_t)(b*SS + q)) * DD + h*DK + c0] = w;
    }
}

// ---------------------------------------------------------------------------
extern "C" void kernel_launch(void* const* d_in, const int* in_sizes, int n_in,
                              void* d_out, int out_size)
{
    const float* q  = (const float*)d_in[0];
    const float* k  = (const float*)d_in[1];
    const float* v  = (const float*)d_in[2];
    // d_in[3] = mask (strict causal tril) — implemented analytically
    const float* Wq = (const float*)d_in[4];
    const float* bq = (const float*)d_in[5];
    const float* Wk = (const float*)d_in[6];
    const float* bk = (const float*)d_in[7];
    const float* Wv = (const float*)d_in[8];
    const float* bv = (const float*)d_in[9];
    const float* Wo = (const float*)d_in[10];
    const float* bo = (const float*)d_in[11];
    float* out = (float*)d_out;

    float *pQh, *pKh, *pVh, *pCtx;
    cudaGetSymbolAddress((void**)&pQh,  g_Qh);
    cudaGetSymbolAddress((void**)&pKh,  g_Kh);
    cudaGetSymbolAddress((void**)&pVh,  g_Vh);
    cudaGetSymbolAddress((void**)&pCtx, g_Ctx);

    dim3 gGemm(DD/128, MT/128);   // (8, 32)
    dim3 blk(256);

    sgemm_proj<1><<<gGemm, blk>>>(q, Wq, bq, pQh);
    sgemm_proj<1><<<gGemm, blk>>>(k, Wk, bk, pKh);
    sgemm_proj<1><<<gGemm, blk>>>(v, Wv, bv, pVh);

    dim3 gAttn(SS/64, BB*HH);     // (32, 32)
    attn_causal<<<gAttn, blk>>>(pQh, pKh, pVh, pCtx);

    sgemm_proj<0><<<gGemm, blk>>>(pCtx, Wo, bo, out);
}

// round 10
// speedup vs baseline: 2.3377x; 2.3377x over previous
#include <cuda_runtime.h>
#include <cuda_bf16.h>
#include <mma.h>
#include <cstdint>

using namespace nvcuda;

// Problem constants
#define BB 2
#define SS 2048
#define DD 1024
#define HH 16
#define DK 64
#define MT (BB*SS)      // 4096 token rows

// Scratch (device globals — no allocation allowed)
__device__ float g_Qh[BB*HH*SS*DK];   // [B,H,S,DK] tf32-rounded
__device__ float g_Kh[BB*HH*SS*DK];
__device__ float g_Vh[BB*HH*SS*DK];
__device__ float g_Ctx[BB*SS*DD];     // [B,S,D]  tf32-rounded
__device__ float g_Xr[3*MT*DD];       // rounded q,k,v
__device__ float g_Wr[4*DD*DD];       // rounded Wq,Wk,Wv,Wo

// ---------------------------------------------------------------------------
// helpers
// ---------------------------------------------------------------------------
__device__ __forceinline__ uint32_t smem_u32(const void* p) {
    uint32_t a;
    asm("{ .reg .u64 t; cvta.to.shared.u64 t, %1; cvt.u32.u64 %0, t; }"
        : "=r"(a) : "l"(p));
    return a;
}
__device__ __forceinline__ uint32_t f2tf32(float f) {          // round-to-nearest tf32
    uint32_t u;
    asm("cvt.rna.tf32.f32 %0, %1;" : "=r"(u) : "f"(f));
    return u;
}
__device__ __forceinline__ float rtf32(float f) { return __uint_as_float(f2tf32(f)); }

__device__ __forceinline__ void mma1688(float c[4], const uint32_t a[4],
                                        uint32_t b0, uint32_t b1) {
    asm volatile(
        "mma.sync.aligned.m16n8k8.row.col.f32.tf32.tf32.f32 "
        "{%0,%1,%2,%3}, {%4,%5,%6,%7}, {%8,%9}, {%0,%1,%2,%3};"
        : "+f"(c[0]), "+f"(c[1]), "+f"(c[2]), "+f"(c[3])
        : "r"(a[0]), "r"(a[1]), "r"(a[2]), "r"(a[3]), "r"(b0), "r"(b1));
}

#define CP_ASYNC16(saddr, gptr) \
    asm volatile("cp.async.cg.shared.global [%0], [%1], 16;" \
                 :: "r"((uint32_t)(saddr)), "l"(gptr))
#define CP_COMMIT() asm volatile("cp.async.commit_group;" ::: "memory")
#define CP_WAIT(n)  asm volatile("cp.async.wait_group %0;" :: "n"(n) : "memory")

// ---------------------------------------------------------------------------
// Pre-pass: RNA-round tensors to tf32 (kills truncation bias in HMMA)
// ---------------------------------------------------------------------------
__global__ void prep_round3(const float* __restrict__ a, const float* __restrict__ b,
                            const float* __restrict__ c, float* __restrict__ dst)
{
    const float* src = (blockIdx.z == 0) ? a : (blockIdx.z == 1) ? b : c;
    float* d = dst + (size_t)blockIdx.z * MT * DD;
    int i = blockIdx.x * 256 + threadIdx.x;        // float4 index, 1M total
    float4 v = *(const float4*)&src[i * 4];
    v.x = rtf32(v.x); v.y = rtf32(v.y); v.z = rtf32(v.z); v.w = rtf32(v.w);
    *(float4*)&d[i * 4] = v;
}
__global__ void prep_round4(const float* __restrict__ a, const float* __restrict__ b,
                            const float* __restrict__ c, const float* __restrict__ e,
                            float* __restrict__ dst)
{
    const float* src = (blockIdx.z == 0) ? a : (blockIdx.z == 1) ? b
                     : (blockIdx.z == 2) ? c : e;
    float* d = dst + (size_t)blockIdx.z * DD * DD;
    int i = blockIdx.x * 256 + threadIdx.x;        // float4 index, 256K total
    float4 v = *(const float4*)&src[i * 4];
    v.x = rtf32(v.x); v.y = rtf32(v.y); v.z = rtf32(v.z); v.w = rtf32(v.w);
    *(float4*)&d[i * 4] = v;
}

// ---------------------------------------------------------------------------
// wmma tf32 GEMM: C[4096,1024] = A @ W + bias. A,W pre-rounded to tf32.
// 128x128 CTA tile, BK=32, 8 warps (2x4 warp grid of 32x64 warp tiles).
// MODE 0: row-major output (final, fp32).  MODE 1: head-split, tf32-rounded.
// ---------------------------------------------------------------------------
#define GBK 32
#define ALD 40    // A smem row stride (floats)
#define BLD 136   // B smem row stride (floats)
#define GA_STAGE (128*ALD)
#define GB_STAGE (GBK*BLD)
#define GSMEM_F  (2*GA_STAGE + 2*GB_STAGE)   // 18944 floats = 75776 B

template<int MODE>
__global__ void __launch_bounds__(256, 1)
gemm_tc(const float* __restrict__ A, const float* __restrict__ B,
        const float* __restrict__ bias, float* __restrict__ C)
{
    extern __shared__ __align__(128) float sm[];
    float* As = sm;                    // [2][128][40]
    float* Bs = sm + 2 * GA_STAGE;     // [2][32][136]
    const uint32_t sAs = smem_u32(As);
    const uint32_t sBs = smem_u32(Bs);

    const int tid = threadIdx.x;
    const int w = tid >> 5;
    const int wr = w >> 1;            // 0..3  -> rows 32*wr
    const int wc = w & 1;             // 0..1  -> cols 64*wc
    const int row0 = blockIdx.y * 128;
    const int col0 = blockIdx.x * 128;

    wmma::fragment<wmma::accumulator, 16, 16, 8, float> acc[2][4];
    #pragma unroll
    for (int i = 0; i < 2; i++)
        #pragma unroll
        for (int j = 0; j < 4; j++) wmma::fill_fragment(acc[i][j], 0.f);

    auto loadA = [&](int ks, int buf) {
        const float* Ag = A + (size_t)row0 * DD + ks * GBK;
        const uint32_t dst = sAs + buf * GA_STAGE * 4;
        #pragma unroll
        for (int u = 0; u < 4; u++) {
            int c = u * 256 + tid;             // 1024 chunks
            int r = c >> 3, ch = c & 7;
            CP_ASYNC16(dst + r * (ALD*4) + ch * 16, Ag + (size_t)r * DD + ch * 4);
        }
    };
    auto loadB = [&](int ks, int buf) {
        const float* Bg = B + (size_t)(ks * GBK) * DD + col0;
        const uint32_t dst = sBs + buf * GB_STAGE * 4;
        #pragma unroll
        for (int u = 0; u < 4; u++) {
            int c = u * 256 + tid;             // 1024 chunks
            int r = c >> 5, ch = c & 31;
            CP_ASYNC16(dst + r * (BLD*4) + ch * 16, Bg + (size_t)r * DD + ch * 4);
        }
    };

    loadA(0, 0); loadB(0, 0); CP_COMMIT();

    const int NK = DD / GBK;          // 32
    for (int ks = 0; ks < NK; ks++) {
        if (ks + 1 < NK) {
            loadA(ks + 1, (ks + 1) & 1);
            loadB(ks + 1, (ks + 1) & 1);
            CP_COMMIT();
            CP_WAIT(1);
        } else {
            CP_WAIT(0);
        }
        __syncthreads();

        const float* Ab = As + (ks & 1) * GA_STAGE + wr * 32 * ALD;
        const float* Bb = Bs + (ks & 1) * GB_STAGE + wc * 64;
        #pragma unroll
        for (int kk = 0; kk < 4; kk++) {
            wmma::fragment<wmma::matrix_a, 16, 16, 8, wmma::precision::tf32,
                           wmma::row_major> fa[2];
            wmma::fragment<wmma::matrix_b, 16, 16, 8, wmma::precision::tf32,
                           wmma::row_major> fb[4];
            #pragma unroll
            for (int im = 0; im < 2; im++)
                wmma::load_matrix_sync(fa[im], Ab + im * 16 * ALD + kk * 8, ALD);
            #pragma unroll
            for (int in = 0; in < 4; in++)
                wmma::load_matrix_sync(fb[in], Bb + kk * 8 * BLD + in * 16, BLD);
            #pragma unroll
            for (int im = 0; im < 2; im++)
                #pragma unroll
                for (int in = 0; in < 4; in++)
                    wmma::mma_sync(acc[im][in], fa[im], fb[in], acc[im][in]);
        }
        __syncthreads();
    }

    // Epilogue: stage C in smem (reuse As/Bs space), ld = 136
    #pragma unroll
    for (int im = 0; im < 2; im++)
        #pragma unroll
        for (int in = 0; in < 4; in++)
            wmma::store_matrix_sync(&sm[(wr*32 + im*16) * 136 + wc*64 + in*16],
                                    acc[im][in], 136, wmma::mem_row_major);
    __syncthreads();

    #pragma unroll
    for (int u = 0; u < 16; u++) {
        int id = u * 256 + tid;                 // 4096 float4s
        int r  = id >> 5;
        int c4 = (id & 31) * 4;
        float4 vv = *(const float4*)&sm[r * 136 + c4];
        const int col = col0 + c4;
        vv.x += bias[col];  vv.y += bias[col+1];
        vv.z += bias[col+2]; vv.w += bias[col+3];
        const int trow = row0 + r;
        if (MODE == 0) {
            *(float4*)&C[(size_t)trow * DD + col] = vv;
        } else {
            vv.x = rtf32(vv.x); vv.y = rtf32(vv.y);
            vv.z = rtf32(vv.z); vv.w = rtf32(vv.w);
            const int b = trow >> 11;
            const int s = trow & (SS - 1);
            const int h = col >> 6;
            const int dk = col & (DK - 1);
            *(float4*)&C[(((size_t)(b*HH + h))*SS + s)*DK + dk] = vv;
        }
    }
}

// ---------------------------------------------------------------------------
// Flash attention with mma.sync tf32. CTA = (bh, 128-query tile), 8 warps,
// each warp owns 16 query rows. Q frags register-resident; K/V double-buffered
// cp.async; P round-trips through smem (layout change + tf32 rounding).
// Causal: tiles kt <= 2qt+1; per-element mask only when kt >= 2qt.
// ---------------------------------------------------------------------------
#define APAD 68
#define AT_SMEM_F (128*APAD + 4*64*APAD)    // Ps + 2xKs + 2xVs = 26112 floats

__global__ void __launch_bounds__(256)
attn_tc(const float* __restrict__ Qh, const float* __restrict__ Kh,
        const float* __restrict__ Vh, float* __restrict__ Ctx)
{
    extern __shared__ __align__(128) float sm[];
    float* Ps = sm;                         // [128][68]  (also Q staging)
    float* Ks = sm + 128*APAD;              // [2][64][68]
    float* Vs = Ks + 2*64*APAD;             // [2][64][68]
    const uint32_t sPs = smem_u32(Ps);
    const uint32_t sKs = smem_u32(Ks);
    const uint32_t sVs = smem_u32(Vs);

    const int bh = blockIdx.x;
    const int qt = (gridDim.y - 1) - blockIdx.y;    // big tiles first
    const int b  = bh >> 4;
    const int h  = bh & (HH - 1);

    const int tid  = threadIdx.x;
    const int w    = tid >> 5;
    const int lane = tid & 31;
    const int g    = lane >> 2;       // group id (row within fragment)
    const int t    = lane & 3;        // thread in group
    const int r0   = w * 16;          // warp's first local query row

    const float* Qp = Qh + (size_t)bh * SS * DK + (size_t)qt * 128 * DK;
    const float* Kp = Kh + (size_t)bh * SS * DK;
    const float* Vp = Vh + (size_t)bh * SS * DK;

    // stage Q tile 128x64 into Ps
    #pragma unroll
    for (int u = 0; u < 8; u++) {
        int c = u * 256 + tid;                 // 2048 float4 chunks
        int row = c >> 4, c4 = (c & 15) * 4;
        *(float4*)&Ps[row * APAD + c4] = *(const float4*)&Qp[(size_t)row * DK + c4];
    }
    __syncthreads();

    // Q fragments, scale folded in (log2 domain: 1/sqrt(64) * log2(e))
    const float SCL = 0.125f * 1.44269504088896f;
    uint32_t qf[8][4];
    #pragma unroll
    for (int ks = 0; ks < 8; ks++) {
        int k0 = ks * 8;
        qf[ks][0] = f2tf32(Ps[(r0+g  )*APAD + k0 + t    ] * SCL);
        qf[ks][1] = f2tf32(Ps[(r0+g+8)*APAD + k0 + t    ] * SCL);
        qf[ks][2] = f2tf32(Ps[(r0+g  )*APAD + k0 + t + 4] * SCL);
        qf[ks][3] = f2tf32(Ps[(r0+g+8)*APAD + k0 + t + 4] * SCL);
    }
    __syncthreads();

    float m0 = -1e30f, m1 = -1e30f, l0 = 0.f, l1 = 0.f;
    float Oa[8][4];
    #pragma unroll
    for (int f = 0; f < 8; f++)
        #pragma unroll
        for (int r = 0; r < 4; r++) Oa[f][r] = 0.f;

    const int ktmax = 2 * qt + 1;

    // K/V tile loader (64x64 each) into buffer `buf`
    auto load_kv = [&](int kt, int buf) {
        const uint32_t dK = sKs + buf * (64*APAD*4);
        const uint32_t dV = sVs + buf * (64*APAD*4);
        #pragma unroll
        for (int u = 0; u < 4; u++) {
            int c = u * 256 + tid;            // 1024 chunks each
            int row = c >> 4, ch = c & 15;
            CP_ASYNC16(dK + row*(APAD*4) + ch*16,
                       Kp + (size_t)(kt*64 + row)*DK + ch*4);
            CP_ASYNC16(dV + row*(APAD*4) + ch*16,
                       Vp + (size_t)(kt*64 + row)*DK + ch*4);
        }
        CP_COMMIT();
    };

    load_kv(0, 0);

    for (int kt = 0; kt <= ktmax; kt++) {
        CP_WAIT(0);
        __syncthreads();
        if (kt + 1 <= ktmax) load_kv(kt + 1, (kt + 1) & 1);

        const float* Kb = Ks + (kt & 1) * 64 * APAD;
        const float* Vb = Vs + (kt & 1) * 64 * APAD;

        // S = (Q*scl) @ K^T    (Sa[f]: 16 rows x 8 keys, f = key octet)
        float Sa[8][4];
        #pragma unroll
        for (int f = 0; f < 8; f++)
            #pragma unroll
            for (int r = 0; r < 4; r++) Sa[f][r] = 0.f;
        #pragma unroll
        for (int ks = 0; ks < 8; ks++) {
            int k0 = ks * 8;
            #pragma unroll
            for (int f = 0; f < 8; f++) {
                uint32_t b0 = __float_as_uint(Kb[(f*8 + g)*APAD + k0 + t    ]);
                uint32_t b1 = __float_as_uint(Kb[(f*8 + g)*APAD + k0 + t + 4]);
                mma1688(Sa[f], qf[ks], b0, b1);
            }
        }

        // causal mask (only near/on diagonal)
        if (kt >= 2 * qt) {
            const int grow0 = qt*128 + r0 + g;
            const int grow1 = grow0 + 8;
            #pragma unroll
            for (int f = 0; f < 8; f++) {
                const int c0 = kt*64 + f*8 + 2*t;
                if (c0     > grow0) Sa[f][0] = -1e30f;
                if (c0 + 1 > grow0) Sa[f][1] = -1e30f;
                if (c0     > grow1) Sa[f][2] = -1e30f;
                if (c0 + 1 > grow1) Sa[f][3] = -1e30f;
            }
        }

        // online softmax (log2 domain)
        float mx0 = -1e30f, mx1 = -1e30f;
        #pragma unroll
        for (int f = 0; f < 8; f++) {
            mx0 = fmaxf(mx0, fmaxf(Sa[f][0], Sa[f][1]));
            mx1 = fmaxf(mx1, fmaxf(Sa[f][2], Sa[f][3]));
        }
        mx0 = fmaxf(mx0, __shfl_xor_sync(0xffffffffu, mx0, 1));
        mx0 = fmaxf(mx0, __shfl_xor_sync(0xffffffffu, mx0, 2));
        mx1 = fmaxf(mx1, __shfl_xor_sync(0xffffffffu, mx1, 1));
        mx1 = fmaxf(mx1, __shfl_xor_sync(0xffffffffu, mx1, 2));

        const float mn0 = fmaxf(m0, mx0), mn1 = fmaxf(m1, mx1);
        const float corr0 = exp2f(m0 - mn0), corr1 = exp2f(m1 - mn1);
        float s0 = 0.f, s1 = 0.f;
        #pragma unroll
        for (int f = 0; f < 8; f++) {
            float p00 = exp2f(Sa[f][0] - mn0);
            float p01 = exp2f(Sa[f][1] - mn0);
            float p10 = exp2f(Sa[f][2] - mn1);
            float p11 = exp2f(Sa[f][3] - mn1);
            s0 += p00 + p01;  s1 += p10 + p11;
            float2 v0 = make_float2(rtf32(p00), rtf32(p01));
            float2 v1 = make_float2(rtf32(p10), rtf32(p11));
            *(float2*)&Ps[(r0+g  )*APAD + f*8 + 2*t] = v0;
            *(float2*)&Ps[(r0+g+8)*APAD + f*8 + 2*t] = v1;
        }
        s0 += __shfl_xor_sync(0xffffffffu, s0, 1);
        s0 += __shfl_xor_sync(0xffffffffu, s0, 2);
        s1 += __shfl_xor_sync(0xffffffffu, s1, 1);
        s1 += __shfl_xor_sync(0xffffffffu, s1, 2);
        l0 = l0 * corr0 + s0;  m0 = mn0;
        l1 = l1 * corr1 + s1;  m1 = mn1;

        #pragma unroll
        for (int f = 0; f < 8; f++) {
            Oa[f][0] *= corr0; Oa[f][1] *= corr0;
            Oa[f][2] *= corr1; Oa[f][3] *= corr1;
        }
        __syncwarp();

        // O += P @ V   (A = P from smem, B = V)
        #pragma unroll
        for (int ks = 0; ks < 8; ks++) {
            int k0 = ks * 8;
            uint32_t pa[4];
            pa[0] = __float_as_uint(Ps[(r0+g  )*APAD + k0 + t    ]);
            pa[1] = __float_as_uint(Ps[(r0+g+8)*APAD + k0 + t    ]);
            pa[2] = __float_as_uint(Ps[(r0+g  )*APAD + k0 + t + 4]);
            pa[3] = __float_as_uint(Ps[(r0+g+8)*APAD + k0 + t + 4]);
            #pragma unroll
            for (int f = 0; f < 8; f++) {
                uint32_t b0 = __float_as_uint(Vb[(k0 + t    )*APAD + f*8 + g]);
                uint32_t b1 = __float_as_uint(Vb[(k0 + t + 4)*APAD + f*8 + g]);
                mma1688(Oa[f], pa, b0, b1);
            }
        }
        __syncthreads();
    }

    // normalize + write Ctx [B,S,D], tf32-rounded (feeds final GEMM)
    const float inv0 = 1.f / l0, inv1 = 1.f / l1;
    const int srow0 = qt*128 + r0 + g;
    const int srow1 = srow0 + 8;
    #pragma unroll
    for (int f = 0; f < 8; f++) {
        const int col = h*64 + f*8 + 2*t;
        float2 v0 = make_float2(rtf32(Oa[f][0]*inv0), rtf32(Oa[f][1]*inv0));
        float2 v1 = make_float2(rtf32(Oa[f][2]*inv1), rtf32(Oa[f][3]*inv1));
        *(float2*)&Ctx[((size_t)(b*SS + srow0))*DD + col] = v0;
        *(float2*)&Ctx[((size_t)(b*SS + srow1))*DD + col] = v1;
    }
}

// ---------------------------------------------------------------------------
extern "C" void kernel_launch(void* const* d_in, const int* in_sizes, int n_in,
                              void* d_out, int out_size)
{
    const float* q  = (const float*)d_in[0];
    const float* k  = (const float*)d_in[1];
    const float* v  = (const float*)d_in[2];
    // d_in[3] = mask (strict causal tril) — implemented analytically
    const float* Wq = (const float*)d_in[4];
    const float* bq = (const float*)d_in[5];
    const float* Wk = (const float*)d_in[6];
    const float* bk = (const float*)d_in[7];
    const float* Wv = (const float*)d_in[8];
    const float* bv = (const float*)d_in[9];
    const float* Wo = (const float*)d_in[10];
    const float* bo = (const float*)d_in[11];
    float* out = (float*)d_out;

    float *pQh, *pKh, *pVh, *pCtx, *pXr, *pWr;
    cudaGetSymbolAddress((void**)&pQh,  g_Qh);
    cudaGetSymbolAddress((void**)&pKh,  g_Kh);
    cudaGetSymbolAddress((void**)&pVh,  g_Vh);
    cudaGetSymbolAddress((void**)&pCtx, g_Ctx);
    cudaGetSymbolAddress((void**)&pXr,  g_Xr);
    cudaGetSymbolAddress((void**)&pWr,  g_Wr);

    const int gemm_smem = GSMEM_F * 4;          // 75776 B
    const int attn_smem = AT_SMEM_F * 4;        // 104448 B
    cudaFuncSetAttribute(gemm_tc<0>, cudaFuncAttributeMaxDynamicSharedMemorySize, gemm_smem);
    cudaFuncSetAttribute(gemm_tc<1>, cudaFuncAttributeMaxDynamicSharedMemorySize, gemm_smem);
    cudaFuncSetAttribute(attn_tc,    cudaFuncAttributeMaxDynamicSharedMemorySize, attn_smem);

    // pre-round inputs to tf32 (RNA)
    prep_round3<<<dim3(MT*DD/(4*256), 1, 3), 256>>>(q, k, v, pXr);
    prep_round4<<<dim3(DD*DD/(4*256), 1, 4), 256>>>(Wq, Wk, Wv, Wo, pWr);

    dim3 gGemm(DD/128, MT/128);   // (8, 32)
    gemm_tc<1><<<gGemm, 256, gemm_smem>>>(pXr + 0*(size_t)MT*DD, pWr + 0*DD*DD, bq, pQh);
    gemm_tc<1><<<gGemm, 256, gemm_smem>>>(pXr + 1*(size_t)MT*DD, pWr + 1*DD*DD, bk, pKh);
    gemm_tc<1><<<gGemm, 256, gemm_smem>>>(pXr + 2*(size_t)MT*DD, pWr + 2*DD*DD, bv, pVh);

    dim3 gAttn(BB*HH, SS/128);    // (32, 16), qt reversed inside
    attn_tc<<<gAttn, 256, attn_smem>>>(pQh, pKh, pVh, pCtx);

    gemm_tc<0><<<gGemm, 256, gemm_smem>>>(pCtx, pWr + 3*DD*DD, bo, out);
}

// round 11
// speedup vs baseline: 2.3944x; 1.0243x over previous
#include <cuda_runtime.h>
#include <cuda_bf16.h>
#include <mma.h>
#include <cstdint>

using namespace nvcuda;

// Problem constants
#define BB 2
#define SS 2048
#define DD 1024
#define HH 16
#define DK 64
#define MT (BB*SS)      // 4096 token rows

// Scratch (device globals — no allocation allowed)
__device__ float g_Qh[BB*HH*SS*DK];   // [B,H,S,DK] tf32-rounded
__device__ float g_Kh[BB*HH*SS*DK];
__device__ float g_Vh[BB*HH*SS*DK];
__device__ float g_Ctx[BB*SS*DD];     // [B,S,D]  tf32-rounded
__device__ float g_Xr[3*MT*DD];       // rounded q,k,v
__device__ float g_Wr[4*DD*DD];       // rounded Wq,Wk,Wv,Wo

// ---------------------------------------------------------------------------
// helpers
// ---------------------------------------------------------------------------
__device__ __forceinline__ uint32_t smem_u32(const void* p) {
    uint32_t a;
    asm("{ .reg .u64 t; cvta.to.shared.u64 t, %1; cvt.u32.u64 %0, t; }"
        : "=r"(a) : "l"(p));
    return a;
}
__device__ __forceinline__ uint32_t f2tf32(float f) {          // round-to-nearest tf32
    uint32_t u;
    asm("cvt.rna.tf32.f32 %0, %1;" : "=r"(u) : "f"(f));
    return u;
}
__device__ __forceinline__ float rtf32(float f) { return __uint_as_float(f2tf32(f)); }

__device__ __forceinline__ void mma1688(float c[4], const uint32_t a[4],
                                        uint32_t b0, uint32_t b1) {
    asm volatile(
        "mma.sync.aligned.m16n8k8.row.col.f32.tf32.tf32.f32 "
        "{%0,%1,%2,%3}, {%4,%5,%6,%7}, {%8,%9}, {%0,%1,%2,%3};"
        : "+f"(c[0]), "+f"(c[1]), "+f"(c[2]), "+f"(c[3])
        : "r"(a[0]), "r"(a[1]), "r"(a[2]), "r"(a[3]), "r"(b0), "r"(b1));
}

#define CP_ASYNC16(saddr, gptr) \
    asm volatile("cp.async.cg.shared.global [%0], [%1], 16;" \
                 :: "r"((uint32_t)(saddr)), "l"(gptr))
#define CP_COMMIT() asm volatile("cp.async.commit_group;" ::: "memory")
#define CP_WAIT(n)  asm volatile("cp.async.wait_group %0;" :: "n"(n) : "memory")

// ---------------------------------------------------------------------------
// Pre-pass: RNA-round tensors to tf32 (kills truncation bias in HMMA)
// ---------------------------------------------------------------------------
__global__ void prep_round3(const float* __restrict__ a, const float* __restrict__ b,
                            const float* __restrict__ c, float* __restrict__ dst)
{
    const float* src = (blockIdx.z == 0) ? a : (blockIdx.z == 1) ? b : c;
    float* d = dst + (size_t)blockIdx.z * MT * DD;
    int i = blockIdx.x * 256 + threadIdx.x;        // float4 index, 1M total
    float4 v = *(const float4*)&src[i * 4];
    v.x = rtf32(v.x); v.y = rtf32(v.y); v.z = rtf32(v.z); v.w = rtf32(v.w);
    *(float4*)&d[i * 4] = v;
}
__global__ void prep_round4(const float* __restrict__ a, const float* __restrict__ b,
                            const float* __restrict__ c, const float* __restrict__ e,
                            float* __restrict__ dst)
{
    const float* src = (blockIdx.z == 0) ? a : (blockIdx.z == 1) ? b
                     : (blockIdx.z == 2) ? c : e;
    float* d = dst + (size_t)blockIdx.z * DD * DD;
    int i = blockIdx.x * 256 + threadIdx.x;        // float4 index, 256K total
    float4 v = *(const float4*)&src[i * 4];
    v.x = rtf32(v.x); v.y = rtf32(v.y); v.z = rtf32(v.z); v.w = rtf32(v.w);
    *(float4*)&d[i * 4] = v;
}

// ---------------------------------------------------------------------------
// wmma tf32 GEMM body: C[4096,1024] = A @ W + bias. A,W pre-rounded to tf32.
// 128x128 CTA tile, BK=32, 8 warps (2x4 warp grid of 32x64 warp tiles).
// MODE 0: row-major output (final, fp32).  MODE 1: head-split, tf32-rounded.
// ---------------------------------------------------------------------------
#define GBK 32
#define ALD 40    // A smem row stride (floats)
#define BLD 136   // B smem row stride (floats)
#define GA_STAGE (128*ALD)
#define GB_STAGE (GBK*BLD)
#define GSMEM_F  (2*GA_STAGE + 2*GB_STAGE)   // 18944 floats = 75776 B

template<int MODE>
__device__ __forceinline__ void gemm_body(
    const float* __restrict__ A, const float* __restrict__ B,
    const float* __restrict__ bias, float* __restrict__ C)
{
    extern __shared__ __align__(128) float sm[];
    float* As = sm;                    // [2][128][40]
    float* Bs = sm + 2 * GA_STAGE;     // [2][32][136]
    const uint32_t sAs = smem_u32(As);
    const uint32_t sBs = smem_u32(Bs);

    const int tid = threadIdx.x;
    const int w = tid >> 5;
    const int wr = w >> 1;            // 0..3  -> rows 32*wr
    const int wc = w & 1;             // 0..1  -> cols 64*wc
    const int row0 = blockIdx.y * 128;
    const int col0 = blockIdx.x * 128;

    wmma::fragment<wmma::accumulator, 16, 16, 8, float> acc[2][4];
    #pragma unroll
    for (int i = 0; i < 2; i++)
        #pragma unroll
        for (int j = 0; j < 4; j++) wmma::fill_fragment(acc[i][j], 0.f);

    auto loadA = [&](int ks, int buf) {
        const float* Ag = A + (size_t)row0 * DD + ks * GBK;
        const uint32_t dst = sAs + buf * GA_STAGE * 4;
        #pragma unroll
        for (int u = 0; u < 4; u++) {
            int c = u * 256 + tid;             // 1024 chunks
            int r = c >> 3, ch = c & 7;
            CP_ASYNC16(dst + r * (ALD*4) + ch * 16, Ag + (size_t)r * DD + ch * 4);
        }
    };
    auto loadB = [&](int ks, int buf) {
        const float* Bg = B + (size_t)(ks * GBK) * DD + col0;
        const uint32_t dst = sBs + buf * GB_STAGE * 4;
        #pragma unroll
        for (int u = 0; u < 4; u++) {
            int c = u * 256 + tid;             // 1024 chunks
            int r = c >> 5, ch = c & 31;
            CP_ASYNC16(dst + r * (BLD*4) + ch * 16, Bg + (size_t)r * DD + ch * 4);
        }
    };

    loadA(0, 0); loadB(0, 0); CP_COMMIT();

    const int NK = DD / GBK;          // 32
    for (int ks = 0; ks < NK; ks++) {
        if (ks + 1 < NK) {
            loadA(ks + 1, (ks + 1) & 1);
            loadB(ks + 1, (ks + 1) & 1);
            CP_COMMIT();
            CP_WAIT(1);
        } else {
            CP_WAIT(0);
        }
        __syncthreads();

        const float* Ab = As + (ks & 1) * GA_STAGE + wr * 32 * ALD;
        const float* Bb = Bs + (ks & 1) * GB_STAGE + wc * 64;
        #pragma unroll
        for (int kk = 0; kk < 4; kk++) {
            wmma::fragment<wmma::matrix_a, 16, 16, 8, wmma::precision::tf32,
                           wmma::row_major> fa[2];
            wmma::fragment<wmma::matrix_b, 16, 16, 8, wmma::precision::tf32,
                           wmma::row_major> fb[4];
            #pragma unroll
            for (int im = 0; im < 2; im++)
                wmma::load_matrix_sync(fa[im], Ab + im * 16 * ALD + kk * 8, ALD);
            #pragma unroll
            for (int in = 0; in < 4; in++)
                wmma::load_matrix_sync(fb[in], Bb + kk * 8 * BLD + in * 16, BLD);
            #pragma unroll
            for (int im = 0; im < 2; im++)
                #pragma unroll
                for (int in = 0; in < 4; in++)
                    wmma::mma_sync(acc[im][in], fa[im], fb[in], acc[im][in]);
        }
        __syncthreads();
    }

    // Epilogue: stage C in smem (reuse As/Bs space), ld = 136
    #pragma unroll
    for (int im = 0; im < 2; im++)
        #pragma unroll
        for (int in = 0; in < 4; in++)
            wmma::store_matrix_sync(&sm[(wr*32 + im*16) * 136 + wc*64 + in*16],
                                    acc[im][in], 136, wmma::mem_row_major);
    __syncthreads();

    #pragma unroll
    for (int u = 0; u < 16; u++) {
        int id = u * 256 + tid;                 // 4096 float4s
        int r  = id >> 5;
        int c4 = (id & 31) * 4;
        float4 vv = *(const float4*)&sm[r * 136 + c4];
        const int col = col0 + c4;
        vv.x += bias[col];  vv.y += bias[col+1];
        vv.z += bias[col+2]; vv.w += bias[col+3];
        const int trow = row0 + r;
        if (MODE == 0) {
            *(float4*)&C[(size_t)trow * DD + col] = vv;
        } else {
            vv.x = rtf32(vv.x); vv.y = rtf32(vv.y);
            vv.z = rtf32(vv.z); vv.w = rtf32(vv.w);
            const int b = trow >> 11;
            const int s = trow & (SS - 1);
            const int h = col >> 6;
            const int dk = col & (DK - 1);
            *(float4*)&C[(((size_t)(b*HH + h))*SS + s)*DK + dk] = vv;
        }
    }
}

// Merged QKV projection: grid (8, 32, 3); z selects input/weight/bias/output.
__global__ void __launch_bounds__(256, 2)
gemm_qkv(const float* __restrict__ Xr, const float* __restrict__ Wr,
         const float* __restrict__ bq, const float* __restrict__ bk,
         const float* __restrict__ bv,
         float* __restrict__ Qh, float* __restrict__ Kh, float* __restrict__ Vh)
{
    const int z = blockIdx.z;
    const float* A    = Xr + (size_t)z * MT * DD;
    const float* B    = Wr + (size_t)z * DD * DD;
    const float* bias = (z == 0) ? bq : (z == 1) ? bk : bv;
    float* C          = (z == 0) ? Qh : (z == 1) ? Kh : Vh;
    gemm_body<1>(A, B, bias, C);
}

// Final output projection
__global__ void __launch_bounds__(256, 2)
gemm_out(const float* __restrict__ Ctx, const float* __restrict__ Wr,
         const float* __restrict__ bo, float* __restrict__ C)
{
    gemm_body<0>(Ctx, Wr, bo, C);
}

// ---------------------------------------------------------------------------
// Flash attention with mma.sync tf32. CTA = (bh, 128-query tile), 8 warps,
// each warp owns 16 query rows. Q frags register-resident; K/V double-buffered
// cp.async; P round-trips through smem (layout change + tf32 rounding).
// Causal: tiles kt <= 2qt+1; per-element mask only when kt >= 2qt.
// ---------------------------------------------------------------------------
#define APAD 68
#define AT_SMEM_F (128*APAD + 4*64*APAD)    // Ps + 2xKs + 2xVs = 26112 floats

__global__ void __launch_bounds__(256)
attn_tc(const float* __restrict__ Qh, const float* __restrict__ Kh,
        const float* __restrict__ Vh, float* __restrict__ Ctx)
{
    extern __shared__ __align__(128) float sm[];
    float* Ps = sm;                         // [128][68]  (also Q staging)
    float* Ks = sm + 128*APAD;              // [2][64][68]
    float* Vs = Ks + 2*64*APAD;             // [2][64][68]
    const uint32_t sKs = smem_u32(Ks);
    const uint32_t sVs = smem_u32(Vs);

    const int bh = blockIdx.x;
    const int qt = (gridDim.y - 1) - blockIdx.y;    // big tiles first
    const int b  = bh >> 4;
    const int h  = bh & (HH - 1);

    const int tid  = threadIdx.x;
    const int w    = tid >> 5;
    const int lane = tid & 31;
    const int g    = lane >> 2;       // group id (row within fragment)
    const int t    = lane & 3;        // thread in group
    const int r0   = w * 16;          // warp's first local query row

    const float* Qp = Qh + (size_t)bh * SS * DK + (size_t)qt * 128 * DK;
    const float* Kp = Kh + (size_t)bh * SS * DK;
    const float* Vp = Vh + (size_t)bh * SS * DK;

    // stage Q tile 128x64 into Ps
    #pragma unroll
    for (int u = 0; u < 8; u++) {
        int c = u * 256 + tid;                 // 2048 float4 chunks
        int row = c >> 4, c4 = (c & 15) * 4;
        *(float4*)&Ps[row * APAD + c4] = *(const float4*)&Qp[(size_t)row * DK + c4];
    }
    __syncthreads();

    // Q fragments, scale folded in (log2 domain: 1/sqrt(64) * log2(e))
    const float SCL = 0.125f * 1.44269504088896f;
    uint32_t qf[8][4];
    #pragma unroll
    for (int ks = 0; ks < 8; ks++) {
        int k0 = ks * 8;
        qf[ks][0] = f2tf32(Ps[(r0+g  )*APAD + k0 + t    ] * SCL);
        qf[ks][1] = f2tf32(Ps[(r0+g+8)*APAD + k0 + t    ] * SCL);
        qf[ks][2] = f2tf32(Ps[(r0+g  )*APAD + k0 + t + 4] * SCL);
        qf[ks][3] = f2tf32(Ps[(r0+g+8)*APAD + k0 + t + 4] * SCL);
    }
    __syncthreads();

    float m0 = -1e30f, m1 = -1e30f, l0 = 0.f, l1 = 0.f;
    float Oa[8][4];
    #pragma unroll
    for (int f = 0; f < 8; f++)
        #pragma unroll
        for (int r = 0; r < 4; r++) Oa[f][r] = 0.f;

    const int ktmax = 2 * qt + 1;

    // K/V tile loader (64x64 each) into buffer `buf`
    auto load_kv = [&](int kt, int buf) {
        const uint32_t dK = sKs + buf * (64*APAD*4);
        const uint32_t dV = sVs + buf * (64*APAD*4);
        #pragma unroll
        for (int u = 0; u < 4; u++) {
            int c = u * 256 + tid;            // 1024 chunks each
            int row = c >> 4, ch = c & 15;
            CP_ASYNC16(dK + row*(APAD*4) + ch*16,
                       Kp + (size_t)(kt*64 + row)*DK + ch*4);
            CP_ASYNC16(dV + row*(APAD*4) + ch*16,
                       Vp + (size_t)(kt*64 + row)*DK + ch*4);
        }
        CP_COMMIT();
    };

    load_kv(0, 0);

    for (int kt = 0; kt <= ktmax; kt++) {
        CP_WAIT(0);
        __syncthreads();
        if (kt + 1 <= ktmax) load_kv(kt + 1, (kt + 1) & 1);

        const float* Kb = Ks + (kt & 1) * 64 * APAD;
        const float* Vb = Vs + (kt & 1) * 64 * APAD;

        // S = (Q*scl) @ K^T    (Sa[f]: 16 rows x 8 keys, f = key octet)
        float Sa[8][4];
        #pragma unroll
        for (int f = 0; f < 8; f++)
            #pragma unroll
            for (int r = 0; r < 4; r++) Sa[f][r] = 0.f;
        #pragma unroll
        for (int ks = 0; ks < 8; ks++) {
            int k0 = ks * 8;
            #pragma unroll
            for (int f = 0; f < 8; f++) {
                uint32_t b0 = __float_as_uint(Kb[(f*8 + g)*APAD + k0 + t    ]);
                uint32_t b1 = __float_as_uint(Kb[(f*8 + g)*APAD + k0 + t + 4]);
                mma1688(Sa[f], qf[ks], b0, b1);
            }
        }

        // causal mask (only near/on diagonal)
        if (kt >= 2 * qt) {
            const int grow0 = qt*128 + r0 + g;
            const int grow1 = grow0 + 8;
            #pragma unroll
            for (int f = 0; f < 8; f++) {
                const int c0 = kt*64 + f*8 + 2*t;
                if (c0     > grow0) Sa[f][0] = -1e30f;
                if (c0 + 1 > grow0) Sa[f][1] = -1e30f;
                if (c0     > grow1) Sa[f][2] = -1e30f;
                if (c0 + 1 > grow1) Sa[f][3] = -1e30f;
            }
        }

        // online softmax (log2 domain)
        float mx0 = -1e30f, mx1 = -1e30f;
        #pragma unroll
        for (int f = 0; f < 8; f++) {
            mx0 = fmaxf(mx0, fmaxf(Sa[f][0], Sa[f][1]));
            mx1 = fmaxf(mx1, fmaxf(Sa[f][2], Sa[f][3]));
        }
        mx0 = fmaxf(mx0, __shfl_xor_sync(0xffffffffu, mx0, 1));
        mx0 = fmaxf(mx0, __shfl_xor_sync(0xffffffffu, mx0, 2));
        mx1 = fmaxf(mx1, __shfl_xor_sync(0xffffffffu, mx1, 1));
        mx1 = fmaxf(mx1, __shfl_xor_sync(0xffffffffu, mx1, 2));

        const float mn0 = fmaxf(m0, mx0), mn1 = fmaxf(m1, mx1);
        const float corr0 = exp2f(m0 - mn0), corr1 = exp2f(m1 - mn1);
        float s0 = 0.f, s1 = 0.f;
        #pragma unroll
        for (int f = 0; f < 8; f++) {
            float p00 = exp2f(Sa[f][0] - mn0);
            float p01 = exp2f(Sa[f][1] - mn0);
            float p10 = exp2f(Sa[f][2] - mn1);
            float p11 = exp2f(Sa[f][3] - mn1);
            s0 += p00 + p01;  s1 += p10 + p11;
            float2 v0 = make_float2(rtf32(p00), rtf32(p01));
            float2 v1 = make_float2(rtf32(p10), rtf32(p11));
            *(float2*)&Ps[(r0+g  )*APAD + f*8 + 2*t] = v0;
            *(float2*)&Ps[(r0+g+8)*APAD + f*8 + 2*t] = v1;
        }
        s0 += __shfl_xor_sync(0xffffffffu, s0, 1);
        s0 += __shfl_xor_sync(0xffffffffu, s0, 2);
        s1 += __shfl_xor_sync(0xffffffffu, s1, 1);
        s1 += __shfl_xor_sync(0xffffffffu, s1, 2);
        l0 = l0 * corr0 + s0;  m0 = mn0;
        l1 = l1 * corr1 + s1;  m1 = mn1;

        #pragma unroll
        for (int f = 0; f < 8; f++) {
            Oa[f][0] *= corr0; Oa[f][1] *= corr0;
            Oa[f][2] *= corr1; Oa[f][3] *= corr1;
        }
        __syncwarp();

        // O += P @ V   (A = P from smem, B = V)
        #pragma unroll
        for (int ks = 0; ks < 8; ks++) {
            int k0 = ks * 8;
            uint32_t pa[4];
            pa[0] = __float_as_uint(Ps[(r0+g  )*APAD + k0 + t    ]);
            pa[1] = __float_as_uint(Ps[(r0+g+8)*APAD + k0 + t    ]);
            pa[2] = __float_as_uint(Ps[(r0+g  )*APAD + k0 + t + 4]);
            pa[3] = __float_as_uint(Ps[(r0+g+8)*APAD + k0 + t + 4]);
            #pragma unroll
            for (int f = 0; f < 8; f++) {
                uint32_t b0 = __float_as_uint(Vb[(k0 + t    )*APAD + f*8 + g]);
                uint32_t b1 = __float_as_uint(Vb[(k0 + t + 4)*APAD + f*8 + g]);
                mma1688(Oa[f], pa, b0, b1);
            }
        }
        __syncthreads();
    }

    // normalize + write Ctx [B,S,D], tf32-rounded (feeds final GEMM)
    const float inv0 = 1.f / l0, inv1 = 1.f / l1;
    const int srow0 = qt*128 + r0 + g;
    const int srow1 = srow0 + 8;
    #pragma unroll
    for (int f = 0; f < 8; f++) {
        const int col = h*64 + f*8 + 2*t;
        float2 v0 = make_float2(rtf32(Oa[f][0]*inv0), rtf32(Oa[f][1]*inv0));
        float2 v1 = make_float2(rtf32(Oa[f][2]*inv1), rtf32(Oa[f][3]*inv1));
        *(float2*)&Ctx[((size_t)(b*SS + srow0))*DD + col] = v0;
        *(float2*)&Ctx[((size_t)(b*SS + srow1))*DD + col] = v1;
    }
}

// ---------------------------------------------------------------------------
extern "C" void kernel_launch(void* const* d_in, const int* in_sizes, int n_in,
                              void* d_out, int out_size)
{
    const float* q  = (const float*)d_in[0];
    const float* k  = (const float*)d_in[1];
    const float* v  = (const float*)d_in[2];
    // d_in[3] = mask (strict causal tril) — implemented analytically
    const float* Wq = (const float*)d_in[4];
    const float* bq = (const float*)d_in[5];
    const float* Wk = (const float*)d_in[6];
    const float* bk = (const float*)d_in[7];
    const float* Wv = (const float*)d_in[8];
    const float* bv = (const float*)d_in[9];
    const float* Wo = (const float*)d_in[10];
    const float* bo = (const float*)d_in[11];
    float* out = (float*)d_out;

    float *pQh, *pKh, *pVh, *pCtx, *pXr, *pWr;
    cudaGetSymbolAddress((void**)&pQh,  g_Qh);
    cudaGetSymbolAddress((void**)&pKh,  g_Kh);
    cudaGetSymbolAddress((void**)&pVh,  g_Vh);
    cudaGetSymbolAddress((void**)&pCtx, g_Ctx);
    cudaGetSymbolAddress((void**)&pXr,  g_Xr);
    cudaGetSymbolAddress((void**)&pWr,  g_Wr);

    const int gemm_smem = GSMEM_F * 4;          // 75776 B
    const int attn_smem = AT_SMEM_F * 4;        // 104448 B
    cudaFuncSetAttribute(gemm_qkv, cudaFuncAttributeMaxDynamicSharedMemorySize, gemm_smem);
    cudaFuncSetAttribute(gemm_out, cudaFuncAttributeMaxDynamicSharedMemorySize, gemm_smem);
    cudaFuncSetAttribute(attn_tc,  cudaFuncAttributeMaxDynamicSharedMemorySize, attn_smem);

    // pre-round inputs to tf32 (RNA)
    prep_round3<<<dim3(MT*DD/(4*256), 1, 3), 256>>>(q, k, v, pXr);
    prep_round4<<<dim3(DD*DD/(4*256), 1, 4), 256>>>(Wq, Wk, Wv, Wo, pWr);

    // merged QKV projection: one launch, 768 CTAs
    gemm_qkv<<<dim3(DD/128, MT/128, 3), 256, gemm_smem>>>(
        pXr, pWr, bq, bk, bv, pQh, pKh, pVh);

    dim3 gAttn(BB*HH, SS/128);    // (32, 16), qt reversed inside
    attn_tc<<<gAttn, 256, attn_smem>>>(pQh, pKh, pVh, pCtx);

    gemm_out<<<dim3(DD/128, MT/128), 256, gemm_smem>>>(pCtx, pWr + 3*DD*DD, bo, out);
}